// round 5
// baseline (speedup 1.0000x reference)
#include <cuda_runtime.h>
#include <cstdint>

// RevNet additive coupling: y1 = x1 ; y2 = x2 + x1 @ W
// x rows: [x1(128) | x2(128)] fp32, W: 128x128 fp32, 262144 rows.
//
// R5: tensor cores via base-ISA mma.sync (m16n8k8 TF32 HMMA) — tcgen05 is
// sm_103a-only and this bench compiles for sm_103. cp.async double-buffered
// x1 tiles, W^T stationary in smem (tf32), register accumulators, direct
// register epilogue. Target: memory-bound (~512 MB moved).

#define D 128
#define TILE_M 128
#define THREADS 256
#define P 132   // padded smem row stride in floats (conflict-free fragments)

static constexpr int ROWS_TOTAL = 262144;
static constexpr int NUM_TILES  = ROWS_TOTAL / TILE_M;   // 2048
static constexpr int WT_BYTES   = D * P * 4;             // 67584
static constexpr int XB_BYTES   = TILE_M * P * 4;        // 67584
static constexpr int SM_WT = 0;
static constexpr int SM_X0 = WT_BYTES;
static constexpr int SM_X1 = SM_X0 + XB_BYTES;
static constexpr int SMEM_BYTES = SM_X1 + XB_BYTES;      // 202752 B

__device__ __forceinline__ uint32_t f2tf32(float f) {
    uint32_t r;
    asm("cvt.rna.tf32.f32 %0, %1;" : "=r"(r) : "f"(f));
    return r;
}
__device__ __forceinline__ void cp16(void* smem_dst, const void* gsrc) {
    uint32_t s = (uint32_t)__cvta_generic_to_shared(smem_dst);
    asm volatile("cp.async.cg.shared.global [%0], [%1], 16;" :: "r"(s), "l"(gsrc));
}
__device__ __forceinline__ void mma_tf32(float& d0, float& d1, float& d2, float& d3,
                                         uint32_t a0, uint32_t a1, uint32_t a2, uint32_t a3,
                                         uint32_t b0, uint32_t b1) {
    asm volatile(
        "mma.sync.aligned.m16n8k8.row.col.f32.tf32.tf32.f32 "
        "{%0,%1,%2,%3}, {%4,%5,%6,%7}, {%8,%9}, {%0,%1,%2,%3};"
        : "+f"(d0), "+f"(d1), "+f"(d2), "+f"(d3)
        : "r"(a0), "r"(a1), "r"(a2), "r"(a3), "r"(b0), "r"(b1));
}

__global__ void __launch_bounds__(THREADS, 1)
revnet_hmma_kernel(const float* __restrict__ x,
                   const float* __restrict__ w,
                   float* __restrict__ out)
{
    extern __shared__ float smem[];
    uint32_t* Wt = (uint32_t*)smem;                       // [128 n][P] tf32
    float*    xb[2] = { smem + SM_X0 / 4, smem + SM_X1 / 4 };  // x1 fp32, [128][P]

    const int tid  = threadIdx.x;
    const int wid  = tid >> 5;
    const int lane = tid & 31;
    const int gid  = lane >> 2;   // 0..7
    const int tig  = lane & 3;    // 0..3
    const int wb   = wid << 4;    // warp's 16-token slab base

    // Stage W^T as tf32: Wt[n][k] = tf32(w[k][n]). One-time, coalesced LDG.
    for (int idx = tid; idx < D * D; idx += THREADS) {
        const int k = idx >> 7, n = idx & 127;
        Wt[n * P + k] = f2tf32(w[idx]);
    }

    // Async-load x1 of tile t (fp32, padded rows) into buffer b.
    auto issue_tile = [&](int t, int b) {
        const long rowbase = (long)t * TILE_M;
        float* dst = xb[b];
        #pragma unroll
        for (int i = tid; i < TILE_M * (D / 4); i += THREADS) {
            const int r = i >> 5;           // 32 float4 per row
            const int q = i & 31;
            cp16(dst + r * P + 4 * q, x + (rowbase + r) * 256L + 4 * q);
        }
        asm volatile("cp.async.commit_group;");
    };

    const int start = blockIdx.x;
    if (start < NUM_TILES) issue_tile(start, 0);

    int buf = 0;
    for (int t = start; t < NUM_TILES; t += gridDim.x, buf ^= 1) {
        const int nt_next = t + gridDim.x;
        if (nt_next < NUM_TILES) {
            issue_tile(nt_next, buf ^ 1);
            asm volatile("cp.async.wait_group 1;");
        } else {
            asm volatile("cp.async.wait_group 0;");
        }
        __syncthreads();   // x1 tile (and Wt on iter 0) visible

        const float* x1s = xb[buf];
        const long rowbase = (long)t * TILE_M;

        // y1 = x1: smem -> gmem, coalesced float4.
        #pragma unroll
        for (int i = tid; i < TILE_M * (D / 4); i += THREADS) {
            const int r = i >> 5;
            const int q = i & 31;
            *(float4*)(out + (rowbase + r) * 256L + 4 * q) =
                *(const float4*)(x1s + r * P + 4 * q);
        }

        // Accumulators: 16 n-tiles x (2 rows x 2 cols) per thread.
        float acc[16][4];
        #pragma unroll
        for (int n = 0; n < 16; n++)
            { acc[n][0] = 0.f; acc[n][1] = 0.f; acc[n][2] = 0.f; acc[n][3] = 0.f; }

        const float*    arow0 = x1s + (wb + gid) * P;       // token row gid
        const float*    arow1 = arow0 + 8 * P;              // token row gid+8
        const uint32_t* wtb   = Wt + gid * P + tig;         // frag base into Wt

        for (int ks = 0; ks < 16; ks++) {
            const int k0 = ks * 8 + tig;
            const uint32_t a0 = f2tf32(arow0[k0]);
            const uint32_t a1 = f2tf32(arow1[k0]);
            const uint32_t a2 = f2tf32(arow0[k0 + 4]);
            const uint32_t a3 = f2tf32(arow1[k0 + 4]);

            #pragma unroll
            for (int n = 0; n < 16; n++) {
                const uint32_t* bp = wtb + n * 8 * P + ks * 8;
                const uint32_t b0 = bp[0];
                const uint32_t b1 = bp[4];
                mma_tf32(acc[n][0], acc[n][1], acc[n][2], acc[n][3],
                         a0, a1, a2, a3, b0, b1);
            }
        }

        // Epilogue: y2 = x2 + acc. float2 per (row, n-tile); sector-exact.
        const long r0 = rowbase + wb + gid;
        #pragma unroll
        for (int n = 0; n < 16; n++) {
            const long g0 = r0 * 256L + 128 + n * 8 + 2 * tig;
            const long g1 = g0 + 8 * 256L;
            const float2 x20 = *(const float2*)(x + g0);
            const float2 x21 = *(const float2*)(x + g1);
            float2 o0, o1;
            o0.x = x20.x + acc[n][0];
            o0.y = x20.y + acc[n][1];
            o1.x = x21.x + acc[n][2];
            o1.y = x21.y + acc[n][3];
            *(float2*)(out + g0) = o0;
            *(float2*)(out + g1) = o1;
        }

        __syncthreads();   // all reads of this buffer done before it is refilled
    }
}

extern "C" void kernel_launch(void* const* d_in, const int* in_sizes, int n_in,
                              void* d_out, int out_size)
{
    const float* x = (const float*)d_in[0];   // [8, 32768, 256] fp32
    const float* w = (const float*)d_in[1];   // [128, 128] fp32
    float* out = (float*)d_out;

    cudaFuncSetAttribute(revnet_hmma_kernel,
                         cudaFuncAttributeMaxDynamicSharedMemorySize,
                         SMEM_BYTES);

    revnet_hmma_kernel<<<148, THREADS, SMEM_BYTES>>>(x, w, out);
}

// round 6
// speedup vs baseline: 1.2943x; 1.2943x over previous
#include <cuda_runtime.h>
#include <cstdint>

// RevNet additive coupling: y1 = x1 ; y2 = x2 + x1 @ W
// x rows: [x1(128) | x2(128)] fp32, W: 128x128 fp32, 262144 rows.
//
// R6: m16n8k8 TF32 HMMA, 512 threads (16 warps, occ 25%), cp.async
// double-buffered x1, W^T stationary in smem, x2 prefetched to REGISTERS
// before the mainloop so the epilogue has no exposed DRAM latency.

#define D 128
#define TILE_M 128
#define THREADS 512
#define P 132   // padded smem row stride (floats) -> conflict-free fragments

static constexpr int ROWS_TOTAL = 262144;
static constexpr int NUM_TILES  = ROWS_TOTAL / TILE_M;   // 2048
static constexpr int WT_FLOATS  = D * P;                 // 16896
static constexpr int XB_FLOATS  = TILE_M * P;            // 16896
static constexpr int SMEM_BYTES = (WT_FLOATS + 2 * XB_FLOATS) * 4;  // 202752

__device__ __forceinline__ uint32_t f2tf32(float f) {
    uint32_t r;
    asm("cvt.rna.tf32.f32 %0, %1;" : "=r"(r) : "f"(f));
    return r;
}
__device__ __forceinline__ void cp16(void* smem_dst, const void* gsrc) {
    uint32_t s = (uint32_t)__cvta_generic_to_shared(smem_dst);
    asm volatile("cp.async.cg.shared.global [%0], [%1], 16;" :: "r"(s), "l"(gsrc));
}
__device__ __forceinline__ void mma_tf32(float& d0, float& d1, float& d2, float& d3,
                                         uint32_t a0, uint32_t a1, uint32_t a2, uint32_t a3,
                                         uint32_t b0, uint32_t b1) {
    asm volatile(
        "mma.sync.aligned.m16n8k8.row.col.f32.tf32.tf32.f32 "
        "{%0,%1,%2,%3}, {%4,%5,%6,%7}, {%8,%9}, {%0,%1,%2,%3};"
        : "+f"(d0), "+f"(d1), "+f"(d2), "+f"(d3)
        : "r"(a0), "r"(a1), "r"(a2), "r"(a3), "r"(b0), "r"(b1));
}

__global__ void __launch_bounds__(THREADS, 1)
revnet_hmma_kernel(const float* __restrict__ x,
                   const float* __restrict__ w,
                   float* __restrict__ out)
{
    extern __shared__ float smem[];
    uint32_t* Wt = (uint32_t*)smem;                        // [128 n][P] tf32
    float* xb[2] = { smem + WT_FLOATS, smem + WT_FLOATS + XB_FLOATS };

    const int tid   = threadIdx.x;
    const int wid   = tid >> 5;
    const int lane  = tid & 31;
    const int gid   = lane >> 2;     // 0..7
    const int tig   = lane & 3;      // 0..3
    const int slab  = (wid & 7) << 4;     // m-slab base row (0..112)
    const int nbase = (wid >> 3) << 6;    // n-half base col (0 or 64)

    // Stage W^T as tf32: Wt[n][k] = tf32(w[k][n]). One-time, coalesced LDG.
    for (int idx = tid; idx < D * D; idx += THREADS) {
        const int k = idx >> 7, n = idx & 127;
        Wt[n * P + k] = f2tf32(w[idx]);
    }

    // Async-load x1 of tile t into buffer b (fp32, padded rows).
    auto issue_tile = [&](int t, int b) {
        const long rowbase = (long)t * TILE_M;
        float* dst = xb[b];
        #pragma unroll
        for (int i = tid; i < TILE_M * (D / 4); i += THREADS) {
            const int r = i >> 5;
            const int q = i & 31;
            cp16(dst + r * P + 4 * q, x + (rowbase + r) * 256L + 4 * q);
        }
        asm volatile("cp.async.commit_group;");
    };

    const int start = blockIdx.x;
    if (start < NUM_TILES) issue_tile(start, 0);

    int buf = 0;
    for (int t = start; t < NUM_TILES; t += gridDim.x, buf ^= 1) {
        const int nxt = t + gridDim.x;
        if (nxt < NUM_TILES) {
            issue_tile(nxt, buf ^ 1);
            asm volatile("cp.async.wait_group 1;");
        } else {
            asm volatile("cp.async.wait_group 0;");
        }
        __syncthreads();   // current x1 buffer (and Wt on iter 0) visible

        const float* x1s = xb[buf];
        const long rowbase = (long)t * TILE_M;
        const long r0 = rowbase + slab + gid;      // this thread's first row

        // Prefetch x2 into registers (consumed in epilogue; latency hidden
        // behind y1 copy + mainloop).
        float2 x2r[8][2];
        #pragma unroll
        for (int n = 0; n < 8; n++) {
            const long g0 = r0 * 256L + 128 + nbase + n * 8 + 2 * tig;
            x2r[n][0] = *(const float2*)(x + g0);
            x2r[n][1] = *(const float2*)(x + g0 + 8 * 256L);
        }

        // y1 = x1: smem -> gmem, coalesced float4.
        #pragma unroll
        for (int i = tid; i < TILE_M * (D / 4); i += THREADS) {
            const int r = i >> 5;
            const int q = i & 31;
            *(float4*)(out + (rowbase + r) * 256L + 4 * q) =
                *(const float4*)(x1s + r * P + 4 * q);
        }

        // Mainloop: 8 n-tiles per warp, 16 k-steps.
        float acc[8][4];
        #pragma unroll
        for (int n = 0; n < 8; n++)
            { acc[n][0] = 0.f; acc[n][1] = 0.f; acc[n][2] = 0.f; acc[n][3] = 0.f; }

        const float*    arow0 = x1s + (slab + gid) * P;
        const float*    arow1 = arow0 + 8 * P;
        const uint32_t* wtb   = Wt + (nbase + gid) * P + tig;

        #pragma unroll 4
        for (int ks = 0; ks < 16; ks++) {
            const int k0 = ks * 8 + tig;
            const uint32_t a0 = f2tf32(arow0[k0]);
            const uint32_t a1 = f2tf32(arow1[k0]);
            const uint32_t a2 = f2tf32(arow0[k0 + 4]);
            const uint32_t a3 = f2tf32(arow1[k0 + 4]);

            #pragma unroll
            for (int n = 0; n < 8; n++) {
                const uint32_t* bp = wtb + n * 8 * P + ks * 8;
                mma_tf32(acc[n][0], acc[n][1], acc[n][2], acc[n][3],
                         a0, a1, a2, a3, bp[0], bp[4]);
            }
        }

        // Epilogue: y2 = x2 + acc (x2 already in registers).
        #pragma unroll
        for (int n = 0; n < 8; n++) {
            const long g0 = r0 * 256L + 128 + nbase + n * 8 + 2 * tig;
            float2 o0, o1;
            o0.x = x2r[n][0].x + acc[n][0];
            o0.y = x2r[n][0].y + acc[n][1];
            o1.x = x2r[n][1].x + acc[n][2];
            o1.y = x2r[n][1].y + acc[n][3];
            *(float2*)(out + g0) = o0;
            *(float2*)(out + g0 + 8 * 256L) = o1;
        }

        __syncthreads();   // all smem reads done before buffer refill
    }
}

extern "C" void kernel_launch(void* const* d_in, const int* in_sizes, int n_in,
                              void* d_out, int out_size)
{
    const float* x = (const float*)d_in[0];   // [8, 32768, 256] fp32
    const float* w = (const float*)d_in[1];   // [128, 128] fp32
    float* out = (float*)d_out;

    cudaFuncSetAttribute(revnet_hmma_kernel,
                         cudaFuncAttributeMaxDynamicSharedMemorySize,
                         SMEM_BYTES);

    revnet_hmma_kernel<<<148, THREADS, SMEM_BYTES>>>(x, w, out);
}